// round 7
// baseline (speedup 1.0000x reference)
#include <cuda_runtime.h>
#include <cuda_fp16.h>
#include <cstdint>

#define NN        2048
#define MEM       32
#define HID       256
#define W1S_STRIDE 260   // words; 1040B row, conflict-free fragment gathers

// dynamic smem layout (bytes)
#define OFF_XF    0                       // 8192: [(m,ks)(16)][lane(32)][reg(4)] u32
#define OFF_B1    8192                    // 1024
#define OFF_W2    9216                    // 1024
#define OFF_W1S   10240                   // 33280 (dead after fragment build)
#define OFF_PART  10240                   // 8192, overlays W1S
#define SMEM_TOTAL 43520

// precise sigmoid (epilogue only)
__device__ __forceinline__ float sigmoidf_acc(float x) {
    return __fdividef(1.0f, 1.0f + __expf(-x));
}
// fast sigmoid via MUFU.TANH (GLU1)
__device__ __forceinline__ float sigmoidf_tanh(float x) {
    float t;
    asm("tanh.approx.f32 %0, %1;" : "=f"(t) : "f"(0.5f * x));
    return fmaf(0.5f, t, 0.5f);
}

__device__ __forceinline__ void mma_f16(float c[4],
                                        uint32_t a0, uint32_t a1, uint32_t a2, uint32_t a3,
                                        uint32_t b0, uint32_t b1) {
    asm volatile(
        "mma.sync.aligned.m16n8k16.row.col.f32.f16.f16.f32 "
        "{%0,%1,%2,%3}, {%4,%5,%6,%7}, {%8,%9}, {%0,%1,%2,%3};"
        : "+f"(c[0]), "+f"(c[1]), "+f"(c[2]), "+f"(c[3])
        : "r"(a0), "r"(a1), "r"(a2), "r"(a3), "r"(b0), "r"(b1));
}

__device__ __forceinline__ uint32_t pack16(float x, float y) {
    half2 h = __floats2half2_rn(x, y);
    return *reinterpret_cast<uint32_t*>(&h);
}

__device__ __forceinline__ void cp16(uint32_t dst, const void* src) {
    asm volatile("cp.async.cg.shared.global [%0], [%1], 16;" :: "r"(dst), "l"(src));
}

__global__ __launch_bounds__(256, 5)
void nlm_kernel(const float* __restrict__ state,   // (128, 2048, 32)
                const float* __restrict__ w1,      // (2048, 32, 256)
                const float* __restrict__ b1,      // (2048, 256)
                const float* __restrict__ w2,      // (2048, 128, 2)
                const float* __restrict__ b2,      // (2048, 2)
                const float* __restrict__ Tg,      // (1,)
                float* __restrict__ out)           // (128, 2048)
{
    extern __shared__ char smem[];
    const uint32_t sbase = (uint32_t)__cvta_generic_to_shared(smem);
    uint32_t* XF   = (uint32_t*)(smem + OFF_XF);
    float*    b1s  = (float*)(smem + OFF_B1);
    float*    w2s  = (float*)(smem + OFF_W2);
    float*    W1s  = (float*)(smem + OFF_W1S);
    float*    part = (float*)(smem + OFF_PART);

    const int n    = blockIdx.x;
    const int tid  = threadIdx.x;
    const int w    = tid >> 5;     // warp 0..7, owns GLU pair-tiles {2w, 2w+1}
    const int lane = tid & 31;
    const int q    = lane & 3;
    const int lr   = lane >> 2;

    // ---------------- Prologue ----------------
    const float* W1g = w1 + (size_t)n * (MEM * HID);
    #pragma unroll
    for (int i = 0; i < 8; i++) {
        const int t  = tid + i * 256;
        const int c4 = t & 63;
        const int k  = t >> 6;
        cp16(sbase + OFF_W1S + (k * W1S_STRIDE + 4 * c4) * 4, W1g + k * HID + 4 * c4);
    }
    asm volatile("cp.async.commit_group;");

    // X: 4 x LDG.128 per thread -> fp16 fragments
    const float* Xg = state + (size_t)n * MEM;
    #pragma unroll
    for (int i = 0; i < 4; i++) {
        const int t    = tid + i * 256;
        const int s    = t & 7;          // float4 index in row (k0 = 4s)
        const int brow = t >> 3;         // batch row
        const float4 v = *reinterpret_cast<const float4*>(Xg + (size_t)brow * (NN * MEM) + 4 * s);
        const int p0   = 2 * s;
        const int q0   = p0 & 3;
        const int reg2 = (p0 >> 2) & 1;
        const int ks   = p0 >> 3;
        const int flr  = brow & 7;
        const int reg  = ((brow >> 3) & 1) + 2 * reg2;
        const int m    = brow >> 4;
        const int base = ((m * 2 + ks) * 32 + flr * 4) * 4 + reg;
        XF[base + q0 * 4]       = pack16(v.x, v.y);
        XF[base + (q0 + 1) * 4] = pack16(v.z, v.w);
    }

    // biases / W2 into smem (coalesced, frees registers)
    b1s[tid] = b1[n * 256 + tid];
    w2s[tid] = w2[n * 256 + tid];

    asm volatile("cp.async.wait_group 0;");
    __syncthreads();

    // ---------------- Build W1 fp16 fragments (conflict-free gathers) ----------------
    uint32_t BA[2][2][2], BB[2][2][2];
    #pragma unroll
    for (int p = 0; p < 2; p++) {
        const int colA = (2 * w + p) * 8 + lr;
        const int colB = colA + 128;
        #pragma unroll
        for (int ks = 0; ks < 2; ks++) {
            #pragma unroll
            for (int r = 0; r < 2; r++) {
                const int k = ks * 16 + r * 8 + 2 * q;
                BA[p][ks][r] = pack16(W1s[k * W1S_STRIDE + colA], W1s[(k + 1) * W1S_STRIDE + colA]);
                BB[p][ks][r] = pack16(W1s[k * W1S_STRIDE + colB], W1s[(k + 1) * W1S_STRIDE + colB]);
            }
        }
    }
    __syncthreads();   // all warps done reading W1s; 'part' may now overwrite it

    // ---------------- Mainloop over 8 M-tiles ----------------
    float* myPart = part + w * 256;
    const int hq0 = (2 * w) * 8 + 2 * q;      // tile p=0 g-col
    const int hq1 = hq0 + 8;                  // tile p=1 g-col
    #pragma unroll
    for (int m = 0; m < 8; m++) {
        const uint4 A0 = *reinterpret_cast<const uint4*>(&XF[((m * 2 + 0) * 32 + lane) * 4]);
        const uint4 A1 = *reinterpret_cast<const uint4*>(&XF[((m * 2 + 1) * 32 + lane) * 4]);

        float accLo0, accLo1, accHi0, accHi1;
        {
            const float2 ba = *reinterpret_cast<const float2*>(&b1s[hq0]);
            const float2 bb = *reinterpret_cast<const float2*>(&b1s[128 + hq0]);
            float Ca[4] = {ba.x, ba.y, ba.x, ba.y};
            float Cb[4] = {bb.x, bb.y, bb.x, bb.y};
            mma_f16(Ca, A0.x, A0.y, A0.z, A0.w, BA[0][0][0], BA[0][0][1]);
            mma_f16(Cb, A0.x, A0.y, A0.z, A0.w, BB[0][0][0], BB[0][0][1]);
            mma_f16(Ca, A1.x, A1.y, A1.z, A1.w, BA[0][1][0], BA[0][1][1]);
            mma_f16(Cb, A1.x, A1.y, A1.z, A1.w, BB[0][1][0], BB[0][1][1]);
            const float g0 = Ca[0] * sigmoidf_tanh(Cb[0]);
            const float g1 = Ca[1] * sigmoidf_tanh(Cb[1]);
            const float g2 = Ca[2] * sigmoidf_tanh(Cb[2]);
            const float g3 = Ca[3] * sigmoidf_tanh(Cb[3]);
            const float4 w2f = *reinterpret_cast<const float4*>(&w2s[hq0 * 2]);
            accLo0 = g0 * w2f.x + g1 * w2f.z;
            accLo1 = g0 * w2f.y + g1 * w2f.w;
            accHi0 = g2 * w2f.x + g3 * w2f.z;
            accHi1 = g2 * w2f.y + g3 * w2f.w;
        }
        {
            const float2 ba = *reinterpret_cast<const float2*>(&b1s[hq1]);
            const float2 bb = *reinterpret_cast<const float2*>(&b1s[128 + hq1]);
            float Ca[4] = {ba.x, ba.y, ba.x, ba.y};
            float Cb[4] = {bb.x, bb.y, bb.x, bb.y};
            mma_f16(Ca, A0.x, A0.y, A0.z, A0.w, BA[1][0][0], BA[1][0][1]);
            mma_f16(Cb, A0.x, A0.y, A0.z, A0.w, BB[1][0][0], BB[1][0][1]);
            mma_f16(Ca, A1.x, A1.y, A1.z, A1.w, BA[1][1][0], BA[1][1][1]);
            mma_f16(Cb, A1.x, A1.y, A1.z, A1.w, BB[1][1][0], BB[1][1][1]);
            const float g0 = Ca[0] * sigmoidf_tanh(Cb[0]);
            const float g1 = Ca[1] * sigmoidf_tanh(Cb[1]);
            const float g2 = Ca[2] * sigmoidf_tanh(Cb[2]);
            const float g3 = Ca[3] * sigmoidf_tanh(Cb[3]);
            const float4 w2f = *reinterpret_cast<const float4*>(&w2s[hq1 * 2]);
            accLo0 += g0 * w2f.x + g1 * w2f.z;
            accLo1 += g0 * w2f.y + g1 * w2f.w;
            accHi0 += g2 * w2f.x + g3 * w2f.z;
            accHi1 += g2 * w2f.y + g3 * w2f.w;
        }

        accLo0 += __shfl_xor_sync(0xffffffffu, accLo0, 1);
        accLo0 += __shfl_xor_sync(0xffffffffu, accLo0, 2);
        accLo1 += __shfl_xor_sync(0xffffffffu, accLo1, 1);
        accLo1 += __shfl_xor_sync(0xffffffffu, accLo1, 2);
        accHi0 += __shfl_xor_sync(0xffffffffu, accHi0, 1);
        accHi0 += __shfl_xor_sync(0xffffffffu, accHi0, 2);
        accHi1 += __shfl_xor_sync(0xffffffffu, accHi1, 1);
        accHi1 += __shfl_xor_sync(0xffffffffu, accHi1, 2);
        if (q == 0) {
            const int r0 = m * 16 + lr;
            myPart[r0 * 2 + 0]       = accLo0;
            myPart[r0 * 2 + 1]       = accLo1;
            myPart[(r0 + 8) * 2 + 0] = accHi0;
            myPart[(r0 + 8) * 2 + 1] = accHi1;
        }
    }

    __syncthreads();

    // ---------------- Final: sum 8 warp partials, GLU2 (precise), /T, store ----------------
    if (tid < 128) {
        const float2 b2v = *reinterpret_cast<const float2*>(&b2[n * 2]);
        float y0 = b2v.x;
        float y1 = b2v.y;
        #pragma unroll
        for (int ww = 0; ww < 8; ww++) {
            const float2 pv = *reinterpret_cast<const float2*>(&part[ww * 256 + tid * 2]);
            y0 += pv.x;
            y1 += pv.y;
        }
        out[(size_t)tid * NN + n] = (y0 * sigmoidf_acc(y1)) / Tg[0];
    }
}

extern "C" void kernel_launch(void* const* d_in, const int* in_sizes, int n_in,
                              void* d_out, int out_size) {
    const float* state = (const float*)d_in[0];
    const float* w1    = (const float*)d_in[1];
    const float* b1    = (const float*)d_in[2];
    const float* w2    = (const float*)d_in[3];
    const float* b2    = (const float*)d_in[4];
    const float* T     = (const float*)d_in[5];
    float* out = (float*)d_out;
    cudaFuncSetAttribute(nlm_kernel, cudaFuncAttributeMaxDynamicSharedMemorySize, SMEM_TOTAL);
    nlm_kernel<<<NN, 256, SMEM_TOTAL>>>(state, w1, b1, w2, b2, T, out);
}

// round 8
// speedup vs baseline: 1.1491x; 1.1491x over previous
#include <cuda_runtime.h>
#include <cuda_fp16.h>
#include <cstdint>

#define NN        2048
#define MEM       32
#define HID       256
#define W1S_STRIDE 260   // words; 1040B row, conflict-free fragment gathers

// dynamic smem layout (bytes)
#define OFF_W1S   0
#define SZ_W1S    (32 * W1S_STRIDE * 4)          // 33280
#define OFF_XF    SZ_W1S                         // 33280
#define SZ_XF     (2048 * 4)                     // 8192: [(m,ks)(16)][lane(32)][reg(4)] u32
#define OFF_PART  (OFF_XF + SZ_XF)               // 41472
#define SZ_PART   (8 * 256 * 4)                  // 8192
#define SMEM_TOTAL (OFF_PART + SZ_PART)          // 49664

// precise sigmoid (epilogue only)
__device__ __forceinline__ float sigmoidf_acc(float x) {
    return __fdividef(1.0f, 1.0f + __expf(-x));
}
// fast sigmoid via MUFU.TANH (GLU1)
__device__ __forceinline__ float sigmoidf_tanh(float x) {
    float t;
    asm("tanh.approx.f32 %0, %1;" : "=f"(t) : "f"(0.5f * x));
    return fmaf(0.5f, t, 0.5f);
}

__device__ __forceinline__ void mma_f16(float c[4],
                                        uint32_t a0, uint32_t a1, uint32_t a2, uint32_t a3,
                                        uint32_t b0, uint32_t b1) {
    asm volatile(
        "mma.sync.aligned.m16n8k16.row.col.f32.f16.f16.f32 "
        "{%0,%1,%2,%3}, {%4,%5,%6,%7}, {%8,%9}, {%0,%1,%2,%3};"
        : "+f"(c[0]), "+f"(c[1]), "+f"(c[2]), "+f"(c[3])
        : "r"(a0), "r"(a1), "r"(a2), "r"(a3), "r"(b0), "r"(b1));
}

__device__ __forceinline__ uint32_t pack16(float x, float y) {
    half2 h = __floats2half2_rn(x, y);
    return *reinterpret_cast<uint32_t*>(&h);
}

__device__ __forceinline__ void cp16(uint32_t dst, const void* src) {
    asm volatile("cp.async.cg.shared.global [%0], [%1], 16;" :: "r"(dst), "l"(src));
}

__global__ __launch_bounds__(256, 4)
void nlm_kernel(const float* __restrict__ state,   // (128, 2048, 32)
                const float* __restrict__ w1,      // (2048, 32, 256)
                const float* __restrict__ b1,      // (2048, 256)
                const float* __restrict__ w2,      // (2048, 128, 2)
                const float* __restrict__ b2,      // (2048, 2)
                const float* __restrict__ Tg,      // (1,)
                float* __restrict__ out)           // (128, 2048)
{
    extern __shared__ char smem[];
    const uint32_t sbase = (uint32_t)__cvta_generic_to_shared(smem);
    float*    W1s  = (float*)(smem + OFF_W1S);
    uint32_t* XF   = (uint32_t*)(smem + OFF_XF);
    float*    part = (float*)(smem + OFF_PART);

    const int n    = blockIdx.x;
    const int tid  = threadIdx.x;
    const int w    = tid >> 5;     // warp 0..7, owns GLU pair-tiles {2w, 2w+1}
    const int lane = tid & 31;
    const int q    = lane & 3;
    const int lr   = lane >> 2;

    // ---------------- Prologue ----------------
    const float* W1g = w1 + (size_t)n * (MEM * HID);
    #pragma unroll
    for (int i = 0; i < 8; i++) {
        const int t  = tid + i * 256;
        const int c4 = t & 63;
        const int k  = t >> 6;
        cp16(sbase + OFF_W1S + (k * W1S_STRIDE + 4 * c4) * 4, W1g + k * HID + 4 * c4);
    }
    asm volatile("cp.async.commit_group;");

    // X: 4 x LDG.128 per thread -> fp16 fragments (contiguous-reg layout)
    const float* Xg = state + (size_t)n * MEM;
    #pragma unroll
    for (int i = 0; i < 4; i++) {
        const int t    = tid + i * 256;
        const int s    = t & 7;          // float4 index in row (k0 = 4s)
        const int brow = t >> 3;         // batch row
        const float4 v = *reinterpret_cast<const float4*>(Xg + (size_t)brow * (NN * MEM) + 4 * s);
        const int p0   = 2 * s;          // first k-pair
        const int q0   = p0 & 3;
        const int reg2 = (p0 >> 2) & 1;
        const int ks   = p0 >> 3;
        const int flr  = brow & 7;
        const int reg  = ((brow >> 3) & 1) + 2 * reg2;
        const int m    = brow >> 4;
        // XF[((m*2+ks)*32 + lane)*4 + reg], lane = flr*4 + q
        const int base = ((m * 2 + ks) * 32 + flr * 4) * 4 + reg;
        XF[base + q0 * 4]       = pack16(v.x, v.y);
        XF[base + (q0 + 1) * 4] = pack16(v.z, v.w);
    }

    // per-warp bias / W2 registers
    const int h0 = (2 * w) * 8 + 2 * q;                 // first tile's g-col (even)
    const float2 ba0 = *reinterpret_cast<const float2*>(&b1[n * 256 + h0]);
    const float2 bb0 = *reinterpret_cast<const float2*>(&b1[n * 256 + 128 + h0]);
    const float2 ba1 = *reinterpret_cast<const float2*>(&b1[n * 256 + h0 + 8]);
    const float2 bb1 = *reinterpret_cast<const float2*>(&b1[n * 256 + 136 + h0]);
    const float4 w2f0 = *reinterpret_cast<const float4*>(&w2[n * 256 + h0 * 2]);
    const float4 w2f1 = *reinterpret_cast<const float4*>(&w2[n * 256 + (h0 + 8) * 2]);

    asm volatile("cp.async.wait_group 0;");
    __syncthreads();

    // ---------------- Build W1 fp16 fragments (hi only, conflict-free gathers) ----------------
    uint32_t BA[2][2][2], BB[2][2][2];
    #pragma unroll
    for (int p = 0; p < 2; p++) {
        const int colA = (2 * w + p) * 8 + lr;
        const int colB = colA + 128;
        #pragma unroll
        for (int ks = 0; ks < 2; ks++) {
            #pragma unroll
            for (int r = 0; r < 2; r++) {
                const int k = ks * 16 + r * 8 + 2 * q;
                BA[p][ks][r] = pack16(W1s[k * W1S_STRIDE + colA], W1s[(k + 1) * W1S_STRIDE + colA]);
                BB[p][ks][r] = pack16(W1s[k * W1S_STRIDE + colB], W1s[(k + 1) * W1S_STRIDE + colB]);
            }
        }
    }

    // ---------------- Mainloop over 8 M-tiles ----------------
    float* myPart = part + w * 256;
    #pragma unroll
    for (int m = 0; m < 8; m++) {
        const uint4 A0 = *reinterpret_cast<const uint4*>(&XF[((m * 2 + 0) * 32 + lane) * 4]);
        const uint4 A1 = *reinterpret_cast<const uint4*>(&XF[((m * 2 + 1) * 32 + lane) * 4]);

        float accLo0, accLo1, accHi0, accHi1;
        {
            float Ca[4] = {ba0.x, ba0.y, ba0.x, ba0.y};
            float Cb[4] = {bb0.x, bb0.y, bb0.x, bb0.y};
            mma_f16(Ca, A0.x, A0.y, A0.z, A0.w, BA[0][0][0], BA[0][0][1]);
            mma_f16(Cb, A0.x, A0.y, A0.z, A0.w, BB[0][0][0], BB[0][0][1]);
            mma_f16(Ca, A1.x, A1.y, A1.z, A1.w, BA[0][1][0], BA[0][1][1]);
            mma_f16(Cb, A1.x, A1.y, A1.z, A1.w, BB[0][1][0], BB[0][1][1]);
            const float g0 = Ca[0] * sigmoidf_tanh(Cb[0]);
            const float g1 = Ca[1] * sigmoidf_tanh(Cb[1]);
            const float g2 = Ca[2] * sigmoidf_tanh(Cb[2]);
            const float g3 = Ca[3] * sigmoidf_tanh(Cb[3]);
            accLo0 = g0 * w2f0.x + g1 * w2f0.z;
            accLo1 = g0 * w2f0.y + g1 * w2f0.w;
            accHi0 = g2 * w2f0.x + g3 * w2f0.z;
            accHi1 = g2 * w2f0.y + g3 * w2f0.w;
        }
        {
            float Ca[4] = {ba1.x, ba1.y, ba1.x, ba1.y};
            float Cb[4] = {bb1.x, bb1.y, bb1.x, bb1.y};
            mma_f16(Ca, A0.x, A0.y, A0.z, A0.w, BA[1][0][0], BA[1][0][1]);
            mma_f16(Cb, A0.x, A0.y, A0.z, A0.w, BB[1][0][0], BB[1][0][1]);
            mma_f16(Ca, A1.x, A1.y, A1.z, A1.w, BA[1][1][0], BA[1][1][1]);
            mma_f16(Cb, A1.x, A1.y, A1.z, A1.w, BB[1][1][0], BB[1][1][1]);
            const float g0 = Ca[0] * sigmoidf_tanh(Cb[0]);
            const float g1 = Ca[1] * sigmoidf_tanh(Cb[1]);
            const float g2 = Ca[2] * sigmoidf_tanh(Cb[2]);
            const float g3 = Ca[3] * sigmoidf_tanh(Cb[3]);
            accLo0 += g0 * w2f1.x + g1 * w2f1.z;
            accLo1 += g0 * w2f1.y + g1 * w2f1.w;
            accHi0 += g2 * w2f1.x + g3 * w2f1.z;
            accHi1 += g2 * w2f1.y + g3 * w2f1.w;
        }

        // ---- butterfly-with-rotation quad reduction: 3 SHFL, each lane ends
        // with a distinct fully-reduced value (value index == q) ----
        // round 1 (xor 1): keep x_{bit0}, send the other
        float a = (q & 1) ? accLo1 : accLo0;
        float b = (q & 1) ? accLo0 : accLo1;
        float c = (q & 1) ? accHi1 : accHi0;
        float d = (q & 1) ? accHi0 : accHi1;
        a += __shfl_xor_sync(0xffffffffu, b, 1);
        c += __shfl_xor_sync(0xffffffffu, d, 1);
        // round 2 (xor 2): keep pairsum_{2*bit1+bit0}, send the other
        float u = (q & 2) ? c : a;
        float v = (q & 2) ? a : c;
        u += __shfl_xor_sync(0xffffffffu, v, 2);
        // lane q holds value q: row = m*16 + lr + 8*bit1, out = bit0
        const int row = m * 16 + lr + ((q & 2) << 2);
        myPart[row * 2 + (q & 1)] = u;   // 32 distinct banks: lr*2 + bit1*16 + bit0
    }

    __syncthreads();

    // ---------------- Final: sum 8 warp partials, GLU2 (precise), /T, store ----------------
    if (tid < 128) {
        const float2 b2v = *reinterpret_cast<const float2*>(&b2[n * 2]);
        float y0 = b2v.x;
        float y1 = b2v.y;
        #pragma unroll
        for (int ww = 0; ww < 8; ww++) {
            const float2 pv = *reinterpret_cast<const float2*>(&part[ww * 256 + tid * 2]);
            y0 += pv.x;
            y1 += pv.y;
        }
        out[(size_t)tid * NN + n] = (y0 * sigmoidf_acc(y1)) / Tg[0];
    }
}

extern "C" void kernel_launch(void* const* d_in, const int* in_sizes, int n_in,
                              void* d_out, int out_size) {
    const float* state = (const float*)d_in[0];
    const float* w1    = (const float*)d_in[1];
    const float* b1    = (const float*)d_in[2];
    const float* w2    = (const float*)d_in[3];
    const float* b2    = (const float*)d_in[4];
    const float* T     = (const float*)d_in[5];
    float* out = (float*)d_out;
    cudaFuncSetAttribute(nlm_kernel, cudaFuncAttributeMaxDynamicSharedMemorySize, SMEM_TOTAL);
    nlm_kernel<<<NN, 256, SMEM_TOTAL>>>(state, w1, b1, w2, b2, T, out);
}